// round 4
// baseline (speedup 1.0000x reference)
#include <cuda_runtime.h>
#include <math.h>

#define BATCH 8
#define PRI   24564
#define NC    80        // classes 1..80 (channel slots)
#define CDIM  93
#define TK1   400
#define TK2   200
#define NDET  (NC*TK1)  // 32000
#define OGRID 19
#define NWORD 7         // ceil(400/64)
#define CAP   2048      // candidate capacity for fast top-k path
#define SENT  0x407FFFFFu   // f2u(-1.0f)

// ---------------- scratch (device globals; no allocation allowed) ----------------
__device__ float4       g_boxes[BATCH*PRI];
__device__ unsigned int g_keys[(size_t)BATCH*NC*PRI];    // transformed masked conf, [b][c][p]
__device__ int          g_selIdx[BATCH*NC*TK1];
__device__ unsigned int g_detKey[BATCH*NDET];            // transformed det score per (b, c*400+r)

// order-preserving float<->uint transform (total order, -1 < all positives)
__device__ __forceinline__ unsigned f2u(float f){
    unsigned u = __float_as_uint(f);
    return (u & 0x80000000u) ? ~u : (u | 0x80000000u);
}
__device__ __forceinline__ float u2f(unsigned u){
    return (u & 0x80000000u) ? __uint_as_float(u & 0x7FFFFFFFu) : __uint_as_float(~u);
}

// precise expf even if harness compiles with fast-math
__device__ __forceinline__ float exp_precise(float a){
#if defined(__USE_FAST_MATH__) || defined(__FAST_MATH__)
    return (float)exp((double)a);
#else
    return expf(a);
#endif
}

// ---------------- K1: decode boxes + transpose masked conf into keys ----------------
#define TPRI 32
__global__ void __launch_bounds__(128) k_decode(const float* __restrict__ x){
    __shared__ __align__(16) float tile[TPRI*CDIM];
    int b   = blockIdx.y;
    int pb  = blockIdx.x * TPRI;
    int cnt = min(TPRI, PRI - pb);
    int tid = threadIdx.x, bd = blockDim.x;
    const float* src = x + ((size_t)b*PRI + pb)*CDIM;
    // vectorized tile load: cnt*CDIM is divisible by 4 (32*93=2976, tail 20*93=1860)
    int nv = (cnt*CDIM) >> 2;
    const float4* src4 = (const float4*)src;
    float4* tile4 = (float4*)tile;
    for (int i = tid; i < nv; i += bd) tile4[i] = src4[i];
    __syncthreads();
    if (tid < cnt){
        const float* r = &tile[tid*CDIM];
        float l0=r[0], l1=r[1], l2=r[2], l3=r[3];
        float q0=r[85], q1=r[86], q2=r[87], q3=r[88];
        float v0=r[89], v1=r[90], v2=r[91], v3=r[92];
        float pw  = __fsub_rn(q2,q0), ph = __fsub_rn(q3,q1);
        float pcx = __fmul_rn(0.5f, __fadd_rn(q2,q0));
        float pcy = __fmul_rn(0.5f, __fadd_rn(q3,q1));
        float cx  = __fadd_rn(__fmul_rn(__fmul_rn(l0,pw), v0), pcx);
        float cy  = __fadd_rn(__fmul_rn(__fmul_rn(l1,pw), v1), pcy);  // ref uses pw for cy too
        float w   = __fmul_rn(exp_precise(__fmul_rn(l2,v2)), pw);
        float h   = __fmul_rn(exp_precise(__fmul_rn(l3,v3)), ph);
        float4 bx;
        bx.x = fminf(fmaxf(__fsub_rn(cx, __fmul_rn(0.5f,w)), 0.f), 1.f);
        bx.y = fminf(fmaxf(__fsub_rn(cy, __fmul_rn(0.5f,h)), 0.f), 1.f);
        bx.z = fminf(fmaxf(__fadd_rn(cx, __fmul_rn(0.5f,w)), 0.f), 1.f);
        bx.w = fminf(fmaxf(__fadd_rn(cy, __fmul_rn(0.5f,h)), 0.f), 1.f);
        g_boxes[(size_t)b*PRI + pb + tid] = bx;
    }
    for (int j = tid; j < NC*TPRI; j += bd){
        int c = j >> 5, pl = j & (TPRI-1);
        if (pl < cnt){
            float v = tile[pl*CDIM + 5 + c];
            g_keys[((size_t)(b*NC + c))*PRI + pb + pl] = (v > 0.01f) ? f2u(v) : SENT;
        }
    }
}

// ---------------- bitonic sort (descending) over keys[0..M), M power of 2 ----------------
__device__ void bitonic_desc(unsigned long long* keys, int M){
    const int tid = threadIdx.x, bd = blockDim.x;
    for (int size = 2; size <= M; size <<= 1){
        for (int stride = size >> 1; stride > 0; stride >>= 1){
            __syncthreads();
            for (int i = tid; i < M; i += bd){
                int j = i ^ stride;
                if (j > i){
                    unsigned long long a = keys[i], b = keys[j];
                    bool up = ((i & size) == 0);
                    if (up ? (a < b) : (a > b)){ keys[i] = b; keys[j] = a; }
                }
            }
        }
    }
    __syncthreads();
}

// ---------------- block-wide exact top-K (sorted desc by (value,~index)), 512 threads --------
// hist: 4096 u32 scratch; keys: CAP u64 out. keys[0..K-1] valid after return.
__device__ void topk_sorted(const unsigned* __restrict__ g, int N, int K,
                            unsigned* hist, unsigned long long* keys)
{
    __shared__ unsigned s_prefix;
    __shared__ int s_k, s_above, s_cand, s_stop, s_cnt, s_eqbase, s_sentN;
    __shared__ unsigned wtot[16];
    __shared__ int warpTot[16];
    const int tid = threadIdx.x, bd = blockDim.x;
    const int wid = tid >> 5, lane = tid & 31;

    if (tid == 0){ s_prefix = 0u; s_k = K; s_above = 0; s_cand = 0;
                   s_stop = 0; s_cnt = 0; s_eqbase = 0; s_sentN = 0; }
    for (int i = tid; i < CAP; i += bd) keys[i] = 0ULL;
    __syncthreads();

    const int shifts[3] = {20, 8, 0};
    const int nbs[3]    = {4096, 4096, 256};
    const unsigned pmasks[3] = {0u, 0xFFF00000u, 0xFFFFFF00u};

    for (int L = 0; L < 3; L++){
        const int shift = shifts[L], NB = nbs[L];
        const unsigned pmask = pmasks[L], bmask = (unsigned)(NB - 1);
        for (int i = tid; i < NB; i += bd) hist[i] = 0u;
        __syncthreads();
        const unsigned pref = s_prefix;
        int localSent = 0;
        for (int base = 0; base < N; base += bd){
            int i = base + tid;
            unsigned v = (i < N) ? g[i] : 0u;
            bool inb = (i < N);
            bool isS = inb && (v == SENT);
            if (L == 0) localSent += isS ? 1 : 0;
            bool act = inb && !isS && ((v & pmask) == pref);
            unsigned bin = act ? ((v >> shift) & bmask) : (0x80000000u | (unsigned)lane);
            unsigned grp = __match_any_sync(0xFFFFFFFFu, bin);
            if (act && lane == (__ffs(grp) - 1)) atomicAdd(&hist[bin], (unsigned)__popc(grp));
        }
        if (L == 0){
            #pragma unroll
            for (int o = 16; o; o >>= 1) localSent += __shfl_down_sync(0xFFFFFFFFu, localSent, o);
            if (lane == 0 && localSent) atomicAdd(&s_sentN, localSent);
        }
        __syncthreads();
        if (tid == 0 && s_sentN > 0 && ((SENT & pmask) == pref))
            hist[(SENT >> shift) & bmask] += (unsigned)s_sentN;
        __syncthreads();

        // ---- crossing search over NB bins ----
        const int PT = (NB + bd - 1) / bd;         // bins per thread (8 or 1)
        int b0 = tid * PT;
        unsigned sown = 0;
        int bhi = min(b0 + PT, NB);
        for (int b = b0; b < bhi; b++) sown += hist[b];
        unsigned ssuf = sown;
        #pragma unroll
        for (int o = 1; o < 32; o <<= 1){
            unsigned xv = __shfl_down_sync(0xFFFFFFFFu, ssuf, o);
            if (lane + o < 32) ssuf += xv;
        }
        if (lane == 0) wtot[wid] = ssuf;
        __syncthreads();
        unsigned wab = 0;
        for (int w = wid + 1; w < 16; w++) wab += wtot[w];
        unsigned St = ssuf + wab;          // count in threads >= tid
        unsigned aboveT = St - sown;       // count in threads > tid
        int k = s_k;
        __syncthreads();                   // snapshot k before single-writer update
        if (b0 < NB && (int)St >= k && (int)aboveT < k){
            int running = (int)aboveT;
            for (int b = bhi - 1; b >= b0; b--){
                int c = (int)hist[b];
                if (running < k && running + c >= k){
                    s_prefix = pref | ((unsigned)b << shift);
                    s_k      = k - running;
                    s_above  = s_above + running;
                    s_cand   = s_above + c;
                    if (s_cand <= CAP || shift == 0) s_stop = 1;
                    break;
                }
                running += c;
            }
        }
        __syncthreads();
        if (s_stop) break;
    }

    const int cand = s_cand;
    if (cand <= CAP){
        // fast path: compact all v >= prefix-base (ballot-aggregated), then sort
        const unsigned Tb = s_prefix;
        for (int base = 0; base < N; base += bd){
            int i = base + tid;
            unsigned v = (i < N) ? g[i] : 0u;
            bool pred = (i < N) && (v >= Tb);
            unsigned ball = __ballot_sync(0xFFFFFFFFu, pred);
            int cntw = __popc(ball);
            int wbase = 0;
            if (lane == 0 && cntw) wbase = atomicAdd(&s_cnt, cntw);
            wbase = __shfl_sync(0xFFFFFFFFu, wbase, 0);
            if (pred){
                int off = __popc(ball & ((1u << lane) - 1u));
                keys[wbase + off] = ((unsigned long long)v << 32) | (unsigned)(~(unsigned)i);
            }
        }
        __syncthreads();
        int M = (cand <= 512) ? 512 : ((cand <= 1024) ? 1024 : 2048);
        bitonic_desc(keys, M);
    } else {
        // fallback: exact value T with massive tie count (e.g. sentinel floods)
        const unsigned T = s_prefix;
        const int need = s_k, cntAbove = s_above;
        for (int base = 0; base < N; base += bd){
            int i = base + tid;
            unsigned v = (i < N) ? g[i] : 0u;
            bool pred = (i < N) && (v > T);
            unsigned ball = __ballot_sync(0xFFFFFFFFu, pred);
            int cntw = __popc(ball);
            int wbase = 0;
            if (lane == 0 && cntw) wbase = atomicAdd(&s_cnt, cntw);
            wbase = __shfl_sync(0xFFFFFFFFu, wbase, 0);
            if (pred){
                int off = __popc(ball & ((1u << lane) - 1u));
                keys[wbase + off] = ((unsigned long long)v << 32) | (unsigned)(~(unsigned)i);
            }
        }
        __syncthreads();
        // ordered (lowest index first) pick of `need` elements == T
        for (int base = 0; base < N && s_eqbase < need; base += bd){
            int i = base + tid;
            bool eq = (i < N) && (g[i] == T);
            unsigned ball = __ballot_sync(0xFFFFFFFFu, eq);
            int wpre = __popc(ball & ((1u << lane) - 1u));
            if (lane == 0) warpTot[wid] = __popc(ball);
            __syncthreads();
            int pre = 0;
            for (int w = 0; w < wid; w++) pre += warpTot[w];
            int rank = s_eqbase + pre + wpre;
            if (eq && rank < need)
                keys[cntAbove + rank] = ((unsigned long long)T << 32) | (unsigned)(~(unsigned)i);
            __syncthreads();
            if (tid == 0){ int tot = 0; for (int w = 0; w < 16; w++) tot += warpTot[w]; s_eqbase += tot; }
            __syncthreads();
        }
        __syncthreads();
        bitonic_desc(keys, 512);
    }
}

// IoU > 0.45 test, exact on the boundary band
__device__ __forceinline__ bool iou_gt(const float4& a, float aa, const float4& d, float dd){
    float ix1 = fmaxf(a.x, d.x), iy1 = fmaxf(a.y, d.y);
    float ix2 = fminf(a.z, d.z), iy2 = fminf(a.w, d.w);
    float iw = fmaxf(__fsub_rn(ix2, ix1), 0.0f);
    float ih = fmaxf(__fsub_rn(iy2, iy1), 0.0f);
    float inter = __fmul_rn(iw, ih);
    if (inter <= 0.0f) return false;
    float uni = __fsub_rn(__fadd_rn(aa, dd), inter);
    if (uni <= 0.0f) return false;
    if (inter > 0.46f*uni) return true;
    if (inter < 0.44f*uni) return false;
    return __fdiv_rn(inter, uni) > 0.45f;
}

// ---------------- K2: fused per-(b,c) top-400 + greedy NMS ----------------
__global__ void __launch_bounds__(512) k_class(){
    __shared__ __align__(16) unsigned char smemA[32768];  // hist+keys, later smat
    __shared__ float4 sbox[TK1];
    __shared__ float  sarea[TK1];
    __shared__ float  sS[TK1];
    __shared__ unsigned long long skept[NWORD];
    unsigned*           hist = (unsigned*)smemA;
    unsigned long long* keys = (unsigned long long*)(smemA + 16384);
    unsigned long long* smat = (unsigned long long*)smemA;   // aliases hist+keys after selection

    int bc = blockIdx.x, b = bc / NC, c = bc % NC;
    int tid = threadIdx.x, bd = blockDim.x, wid = tid >> 5;

    topk_sorted(g_keys + (size_t)bc*PRI, PRI, TK1, hist, keys);

    for (int r = tid; r < TK1; r += bd){
        unsigned long long kk = keys[r];
        int idx  = (int)(~(unsigned)(kk & 0xFFFFFFFFu));
        float sc = u2f((unsigned)(kk >> 32));
        float4 bx = g_boxes[(size_t)b*PRI + idx];
        sbox[r] = bx; sS[r] = sc;
        sarea[r] = __fmul_rn(__fsub_rn(bx.z,bx.x), __fsub_rn(bx.w,bx.y));
        g_selIdx[bc*TK1 + r] = idx;
    }
    __syncthreads();   // keys fully consumed; smat may overwrite

    // lower-triangle suppression bitmatrix, 4-row register tiling
    for (int t = tid; t < (TK1/4)*NWORD; t += bd){
        int it = t / NWORD, w = t - it*NWORD;
        int i0 = it*4, j0 = w*64;
        unsigned long long w0=0, w1=0, w2=0, w3=0;
        int jend = min(j0 + 64, i0 + 3);   // largest needed j is i0+2 (row i0+3 needs j<i0+3)
        if (jend > j0){
            float4 a0 = sbox[i0],   a1 = sbox[i0+1], a2 = sbox[i0+2], a3 = sbox[i0+3];
            float  r0 = sarea[i0],  r1 = sarea[i0+1], r2 = sarea[i0+2], r3 = sarea[i0+3];
            for (int j = j0; j < jend; j++){
                float4 d = sbox[j]; float dd = sarea[j];
                unsigned long long bit = 1ULL << (j - j0);
                if (j < i0   && iou_gt(a0, r0, d, dd)) w0 |= bit;
                if (j < i0+1 && iou_gt(a1, r1, d, dd)) w1 |= bit;
                if (j < i0+2 && iou_gt(a2, r2, d, dd)) w2 |= bit;
                if (j < i0+3 && iou_gt(a3, r3, d, dd)) w3 |= bit;
            }
        }
        smat[(i0  )*NWORD + w] = w0;
        smat[(i0+1)*NWORD + w] = w1;
        smat[(i0+2)*NWORD + w] = w2;
        smat[(i0+3)*NWORD + w] = w3;
    }
    __syncthreads();

    // sequential greedy scan; scan-warp varies per block to spread across SMSPs
    int swid = blockIdx.x & 15;
    if (wid == swid){
        int lane = tid & 31;
        unsigned long long keptw = 0;
        unsigned long long row = (lane < NWORD) ? smat[lane] : 0ULL;
        float sc = sS[0];
        for (int i = 0; i < TK1; i++){
            unsigned long long nrow = 0ULL; float nsc = 0.f;
            if (i + 1 < TK1){
                if (lane < NWORD) nrow = smat[(i+1)*NWORD + lane];
                nsc = sS[i+1];
            }
            bool any = __any_sync(0xFFFFFFFFu, (row & keptw) != 0ULL);
            if (sc > 0.01f && !any && lane == (i >> 6)) keptw |= 1ULL << (i & 63);
            row = nrow; sc = nsc;
        }
        if (lane < NWORD) skept[lane] = keptw;
    }
    __syncthreads();

    for (int r = tid; r < TK1; r += bd){
        bool kept = (skept[r >> 6] >> (r & 63)) & 1ULL;
        float sc = kept ? sS[r] : -1.0f;
        g_detKey[(size_t)b*NDET + c*TK1 + r] = f2u(sc);
    }
}

// ---------------- K3: fused per-batch top-200 + rasterize ----------------
__global__ void __launch_bounds__(512) k_det_raster(float* __restrict__ out){
    __shared__ __align__(16) unsigned char smemA[32768];
    __shared__ float sS2[TK2];
    __shared__ int   sCh[TK2];
    __shared__ int4  sCo[TK2];
    __shared__ unsigned char sV[TK2];
    unsigned*           hist = (unsigned*)smemA;
    unsigned long long* keys = (unsigned long long*)(smemA + 16384);
    int b = blockIdx.x, tid = threadIdx.x, bd = blockDim.x;

    topk_sorted(g_detKey + (size_t)b*NDET, NDET, TK2, hist, keys);

    for (int k = tid; k < TK2; k += bd){
        unsigned long long kk = keys[k];
        int fi   = (int)(~(unsigned)(kk & 0xFFFFFFFFu));
        float s  = u2f((unsigned)(kk >> 32));
        int c = fi / TK1, r = fi % TK1;
        int idx = g_selIdx[(b*NC + c)*TK1 + r];
        float4 bx = g_boxes[(size_t)b*PRI + idx];
        int4 co;
        co.x = (int)rintf(__fmul_rn(bx.x, (float)OGRID));
        co.y = (int)rintf(__fmul_rn(bx.y, (float)OGRID));
        co.z = (int)rintf(__fmul_rn(bx.z, (float)OGRID));
        co.w = (int)rintf(__fmul_rn(bx.w, (float)OGRID));
        sS2[k] = s; sCh[k] = c; sCo[k] = co; sV[k] = (s >= 0.6f) ? 1 : 0;
    }
    __syncthreads();

    for (int cell = tid; cell < OGRID*OGRID; cell += bd){
        int y = cell / OGRID, xp = cell % OGRID;
        float* o = out + ((size_t)b*OGRID*OGRID + cell) * 81;
        for (int ch = 0; ch < 81; ch++) o[ch] = 0.0f;
        for (int k = 0; k < TK2; k++){
            if (sV[k]){
                int4 co = sCo[k];
                if (y >= co.y && y < co.w && xp >= co.x && xp < co.z)
                    o[sCh[k]] = sS2[k];     // ascending k: last writer == max k
            }
        }
    }
}

// ---------------- launch ----------------
extern "C" void kernel_launch(void* const* d_in, const int* in_sizes, int n_in,
                              void* d_out, int out_size){
    const float* x = (const float*)d_in[0];
    float* out = (float*)d_out;
    dim3 g1((PRI + TPRI - 1) / TPRI, BATCH);
    k_decode<<<g1, 128>>>(x);
    k_class<<<BATCH*NC, 512>>>();
    k_det_raster<<<BATCH, 512>>>(out);
}

// round 6
// speedup vs baseline: 1.6076x; 1.6076x over previous
#include <cuda_runtime.h>
#include <math.h>

#define BATCH 8
#define PRI   24564
#define NC    80        // classes 1..80 (channel slots)
#define CDIM  93
#define TK1   400
#define TK2   200
#define NDET  (NC*TK1)  // 32000
#define OGRID 19
#define NWORD 7         // ceil(400/64)
#define SENT  0x407FFFFFu   // f2u(-1.0f)
#define BDIM  256
#define KCAP  512       // candidate capacity / sort size

// ---------------- scratch (device globals; no allocation allowed) ----------------
__device__ float4       g_boxes[BATCH*PRI];
__device__ unsigned int g_keys[(size_t)BATCH*NC*PRI];    // transformed masked conf, [b][c][p]
__device__ int          g_selIdx[BATCH*NC*TK1];
__device__ unsigned int g_detKey[BATCH*NDET];            // transformed det score per (b, c*400+r)

// order-preserving float<->uint transform (total order, -1 < all positives)
__device__ __forceinline__ unsigned f2u(float f){
    unsigned u = __float_as_uint(f);
    return (u & 0x80000000u) ? ~u : (u | 0x80000000u);
}
__device__ __forceinline__ float u2f(unsigned u){
    return (u & 0x80000000u) ? __uint_as_float(u & 0x7FFFFFFFu) : __uint_as_float(~u);
}

// precise expf even if harness compiles with fast-math
__device__ __forceinline__ float exp_precise(float a){
#if defined(__USE_FAST_MATH__) || defined(__FAST_MATH__)
    return (float)exp((double)a);
#else
    return expf(a);
#endif
}

// ---------------- K1: decode boxes + transpose masked conf into keys ----------------
#define TPRI 32
__global__ void __launch_bounds__(128) k_decode(const float* __restrict__ x){
    __shared__ __align__(16) float tile[TPRI*CDIM];
    int b   = blockIdx.y;
    int pb  = blockIdx.x * TPRI;
    int cnt = min(TPRI, PRI - pb);
    int tid = threadIdx.x, bd = blockDim.x;
    const float* src = x + ((size_t)b*PRI + pb)*CDIM;
    int nv = (cnt*CDIM) >> 2;
    const float4* src4 = (const float4*)src;
    float4* tile4 = (float4*)tile;
    for (int i = tid; i < nv; i += bd) tile4[i] = src4[i];
    __syncthreads();
    if (tid < cnt){
        const float* r = &tile[tid*CDIM];
        float l0=r[0], l1=r[1], l2=r[2], l3=r[3];
        float q0=r[85], q1=r[86], q2=r[87], q3=r[88];
        float v0=r[89], v1=r[90], v2=r[91], v3=r[92];
        float pw  = __fsub_rn(q2,q0), ph = __fsub_rn(q3,q1);
        float pcx = __fmul_rn(0.5f, __fadd_rn(q2,q0));
        float pcy = __fmul_rn(0.5f, __fadd_rn(q3,q1));
        float cx  = __fadd_rn(__fmul_rn(__fmul_rn(l0,pw), v0), pcx);
        float cy  = __fadd_rn(__fmul_rn(__fmul_rn(l1,pw), v1), pcy);  // ref uses pw for cy too
        float w   = __fmul_rn(exp_precise(__fmul_rn(l2,v2)), pw);
        float h   = __fmul_rn(exp_precise(__fmul_rn(l3,v3)), ph);
        float4 bx;
        bx.x = fminf(fmaxf(__fsub_rn(cx, __fmul_rn(0.5f,w)), 0.f), 1.f);
        bx.y = fminf(fmaxf(__fsub_rn(cy, __fmul_rn(0.5f,h)), 0.f), 1.f);
        bx.z = fminf(fmaxf(__fadd_rn(cx, __fmul_rn(0.5f,w)), 0.f), 1.f);
        bx.w = fminf(fmaxf(__fadd_rn(cy, __fmul_rn(0.5f,h)), 0.f), 1.f);
        g_boxes[(size_t)b*PRI + pb + tid] = bx;
    }
    for (int j = tid; j < NC*TPRI; j += bd){
        int c = j >> 5, pl = j & (TPRI-1);
        if (pl < cnt){
            float v = tile[pl*CDIM + 5 + c];
            g_keys[((size_t)(b*NC + c))*PRI + pb + pl] = (v > 0.01f) ? f2u(v) : SENT;
        }
    }
}

// ---------------- bitonic sort (descending) over keys[0..512) ----------------
__device__ void bitonic_desc512(unsigned long long* keys){
    const int tid = threadIdx.x, bd = blockDim.x;
    for (int size = 2; size <= KCAP; size <<= 1){
        for (int stride = size >> 1; stride > 0; stride >>= 1){
            __syncthreads();
            for (int i = tid; i < KCAP; i += bd){
                int j = i ^ stride;
                if (j > i){
                    unsigned long long a = keys[i], b = keys[j];
                    bool up = ((i & size) == 0);
                    if (up ? (a < b) : (a > b)){ keys[i] = b; keys[j] = a; }
                }
            }
        }
    }
    __syncthreads();
}

// ---------------- block-wide exact top-K (sorted desc by (value,~index)), 256 threads --------
// N must be divisible by 4. hist: 4096 u32 scratch; keys: 512 u64 out (top K valid, sorted).
__device__ void topk_sorted(const unsigned* __restrict__ g, int N, int K,
                            unsigned* hist, unsigned long long* keys)
{
    __shared__ unsigned s_prefix;
    __shared__ int s_k, s_above, s_cand, s_stop, s_cnt, s_eqbase, s_sentN;
    __shared__ unsigned wtot[8];
    __shared__ int warpTot[8];
    const int tid = threadIdx.x, bd = BDIM;
    const int wid = tid >> 5, lane = tid & 31;
    const uint4* g4 = (const uint4*)g;
    const int N4 = N >> 2;

    if (tid == 0){ s_prefix = 0u; s_k = K; s_above = 0; s_cand = 0;
                   s_stop = 0; s_cnt = 0; s_eqbase = 0; s_sentN = 0; }
    for (int i = tid; i < KCAP; i += bd) keys[i] = 0ULL;
    __syncthreads();

    const int shifts[3] = {20, 8, 0};
    const int nbs[3]    = {4096, 4096, 256};
    const unsigned pmasks[3] = {0u, 0xFFF00000u, 0xFFFFFF00u};

    for (int L = 0; L < 3; L++){
        const int shift = shifts[L], NB = nbs[L];
        const unsigned pmask = pmasks[L], bmask = (unsigned)(NB - 1);
        for (int i = tid; i < NB; i += bd) hist[i] = 0u;
        __syncthreads();
        const unsigned pref = s_prefix;
        int localSent = 0;
        for (int i4 = tid; i4 < N4; i4 += bd){        // atomics only: divergence safe
            uint4 v = g4[i4];
            #pragma unroll
            for (int c = 0; c < 4; c++){
                unsigned vv = (c==0)?v.x:(c==1)?v.y:(c==2)?v.z:v.w;
                bool isS = (vv == SENT);
                if (L == 0) localSent += isS ? 1 : 0;
                if (!isS && ((vv & pmask) == pref))
                    atomicAdd(&hist[(vv >> shift) & bmask], 1u);
            }
        }
        if (L == 0){
            #pragma unroll
            for (int o = 16; o; o >>= 1) localSent += __shfl_down_sync(0xFFFFFFFFu, localSent, o);
            if (lane == 0 && localSent) atomicAdd(&s_sentN, localSent);
        }
        __syncthreads();
        if (tid == 0 && s_sentN > 0 && ((SENT & pmask) == pref))
            hist[(SENT >> shift) & bmask] += (unsigned)s_sentN;
        __syncthreads();

        // ---- crossing search over NB bins ----
        const int PT = NB / bd;               // 16 or 1
        int b0 = tid * PT;
        unsigned sown = 0;
        for (int b = b0; b < b0 + PT; b++) sown += hist[b];
        unsigned ssuf = sown;
        #pragma unroll
        for (int o = 1; o < 32; o <<= 1){
            unsigned xv = __shfl_down_sync(0xFFFFFFFFu, ssuf, o);
            if (lane + o < 32) ssuf += xv;
        }
        if (lane == 0) wtot[wid] = ssuf;
        __syncthreads();
        unsigned wab = 0;
        for (int w = wid + 1; w < 8; w++) wab += wtot[w];
        unsigned St = ssuf + wab;          // count in threads >= tid
        unsigned aboveT = St - sown;       // count in threads > tid
        int k = s_k;
        __syncthreads();                   // snapshot k before single-writer update
        if ((int)St >= k && (int)aboveT < k){
            int running = (int)aboveT;
            for (int b = b0 + PT - 1; b >= b0; b--){
                int c = (int)hist[b];
                if (running < k && running + c >= k){
                    s_prefix = pref | ((unsigned)b << shift);
                    s_k      = k - running;
                    s_above  = s_above + running;
                    s_cand   = s_above + c;
                    if (s_cand <= KCAP || shift == 0) s_stop = 1;
                    break;
                }
                running += c;
            }
        }
        __syncthreads();
        if (s_stop) break;
    }

    const int cand = s_cand;
    if (cand <= KCAP){
        // fast path: compact all v >= prefix-base. UNIFORM trip count: every
        // thread executes every iteration so full-mask ballots are legal.
        const unsigned Tb = s_prefix;
        for (int base = 0; base < N4; base += bd){
            int i4 = base + tid;
            bool inb = (i4 < N4);
            uint4 v = inb ? g4[i4] : make_uint4(0u,0u,0u,0u);
            #pragma unroll
            for (int c = 0; c < 4; c++){
                unsigned vv = (c==0)?v.x:(c==1)?v.y:(c==2)?v.z:v.w;
                bool pred = inb && (vv >= Tb);
                unsigned ball = __ballot_sync(0xFFFFFFFFu, pred);
                int cntw = __popc(ball);
                int wbase = 0;
                if (lane == 0 && cntw) wbase = atomicAdd(&s_cnt, cntw);
                wbase = __shfl_sync(0xFFFFFFFFu, wbase, 0);
                if (pred){
                    int off = __popc(ball & ((1u << lane) - 1u));
                    unsigned idx = (unsigned)(i4*4 + c);
                    keys[wbase + off] = ((unsigned long long)vv << 32) | (~idx);
                }
            }
        }
        __syncthreads();
        bitonic_desc512(keys);
    } else {
        // fallback: exact value T with massive tie count
        const unsigned T = s_prefix;
        const int need = s_k, cntAbove = s_above;
        for (int base = 0; base < N4; base += bd){
            int i4 = base + tid;
            bool inb = (i4 < N4);
            uint4 v = inb ? g4[i4] : make_uint4(0u,0u,0u,0u);
            #pragma unroll
            for (int c = 0; c < 4; c++){
                unsigned vv = (c==0)?v.x:(c==1)?v.y:(c==2)?v.z:v.w;
                bool pred = inb && (vv > T);
                unsigned ball = __ballot_sync(0xFFFFFFFFu, pred);
                int cntw = __popc(ball);
                int wbase = 0;
                if (lane == 0 && cntw) wbase = atomicAdd(&s_cnt, cntw);
                wbase = __shfl_sync(0xFFFFFFFFu, wbase, 0);
                if (pred){
                    int off = __popc(ball & ((1u << lane) - 1u));
                    unsigned idx = (unsigned)(i4*4 + c);
                    keys[wbase + off] = ((unsigned long long)vv << 32) | (~idx);
                }
            }
        }
        __syncthreads();
        // ordered (lowest index first) pick of `need` elements == T
        for (int base = 0; base < N && s_eqbase < need; base += bd){
            int i = base + tid;
            bool eq = (i < N) && (g[i] == T);
            unsigned ball = __ballot_sync(0xFFFFFFFFu, eq);
            int wpre = __popc(ball & ((1u << lane) - 1u));
            if (lane == 0) warpTot[wid] = __popc(ball);
            __syncthreads();
            int pre = 0;
            for (int w = 0; w < wid; w++) pre += warpTot[w];
            int rank = s_eqbase + pre + wpre;
            if (eq && rank < need)
                keys[cntAbove + rank] = ((unsigned long long)T << 32) | (unsigned)(~(unsigned)i);
            __syncthreads();
            if (tid == 0){ int tot = 0; for (int w = 0; w < 8; w++) tot += warpTot[w]; s_eqbase += tot; }
            __syncthreads();
        }
        __syncthreads();
        bitonic_desc512(keys);
    }
}

// IoU > 0.45 test, exact on the boundary band
__device__ __forceinline__ bool iou_gt(const float4& a, float aa, const float4& d, float dd){
    float ix1 = fmaxf(a.x, d.x), iy1 = fmaxf(a.y, d.y);
    float ix2 = fminf(a.z, d.z), iy2 = fminf(a.w, d.w);
    float iw = fmaxf(__fsub_rn(ix2, ix1), 0.0f);
    float ih = fmaxf(__fsub_rn(iy2, iy1), 0.0f);
    float inter = __fmul_rn(iw, ih);
    if (inter <= 0.0f) return false;
    float uni = __fsub_rn(__fadd_rn(aa, dd), inter);
    if (uni <= 0.0f) return false;
    if (inter > 0.46f*uni) return true;
    if (inter < 0.44f*uni) return false;
    return __fdiv_rn(inter, uni) > 0.45f;
}

// ---------------- K2: fused per-(b,c) top-400 + greedy NMS ----------------
#define SMEMA_BYTES 22528   // max(hist 16K + keys 4K = 20480, smat 22400)
__global__ void __launch_bounds__(BDIM, 5) k_class(){
    __shared__ __align__(16) unsigned char smemA[SMEMA_BYTES];
    __shared__ float4 sbox[TK1];
    __shared__ float  sarea[TK1];
    __shared__ float  sS[TK1];
    __shared__ unsigned long long skept[NWORD];
    unsigned*           hist = (unsigned*)smemA;
    unsigned long long* keys = (unsigned long long*)(smemA + 16384);
    unsigned long long* smat = (unsigned long long*)smemA;   // aliases hist+keys after selection

    int bc = blockIdx.x, b = bc / NC, c = bc % NC;
    int tid = threadIdx.x, bd = blockDim.x, wid = tid >> 5;

    topk_sorted(g_keys + (size_t)bc*PRI, PRI, TK1, hist, keys);

    for (int r = tid; r < TK1; r += bd){
        unsigned long long kk = keys[r];
        int idx  = (int)(~(unsigned)(kk & 0xFFFFFFFFu));
        float sc = u2f((unsigned)(kk >> 32));
        float4 bx = g_boxes[(size_t)b*PRI + idx];
        sbox[r] = bx; sS[r] = sc;
        sarea[r] = __fmul_rn(__fsub_rn(bx.z,bx.x), __fsub_rn(bx.w,bx.y));
        g_selIdx[bc*TK1 + r] = idx;
    }
    __syncthreads();   // keys fully consumed; smat may overwrite

    // lower-triangle suppression bitmatrix: bit (i,j) = iou(i,j) > 0.45, j < i
    for (int t = tid; t < TK1*NWORD; t += bd){
        int i = t / NWORD, w = t - i*NWORD;
        int j0 = w*64, j1 = min(i, j0 + 64);
        unsigned long long word = 0;
        if (j1 > j0){
            float4 a = sbox[i]; float ai = sarea[i];
            for (int j = j0; j < j1; j++){
                if (iou_gt(a, ai, sbox[j], sarea[j])) word |= 1ULL << (j - j0);
            }
        }
        smat[i*NWORD + w] = word;
    }
    __syncthreads();

    // sequential greedy scan; scan-warp varies per block to spread across SMSPs
    int swid = blockIdx.x & 7;
    if (wid == swid){
        int lane = tid & 31;
        unsigned long long keptw = 0;
        unsigned long long row = (lane < NWORD) ? smat[lane] : 0ULL;
        float sc = sS[0];
        for (int i = 0; i < TK1; i++){
            unsigned long long nrow = 0ULL; float nsc = 0.f;
            if (i + 1 < TK1){
                if (lane < NWORD) nrow = smat[(i+1)*NWORD + lane];
                nsc = sS[i+1];
            }
            bool any = __any_sync(0xFFFFFFFFu, (row & keptw) != 0ULL);
            if (sc > 0.01f && !any && lane == (i >> 6)) keptw |= 1ULL << (i & 63);
            row = nrow; sc = nsc;
        }
        if (lane < NWORD) skept[lane] = keptw;
    }
    __syncthreads();

    for (int r = tid; r < TK1; r += bd){
        bool kept = (skept[r >> 6] >> (r & 63)) & 1ULL;
        float sc = kept ? sS[r] : -1.0f;
        g_detKey[(size_t)b*NDET + c*TK1 + r] = f2u(sc);
    }
}

// ---------------- K3: fused per-batch top-200 + rasterize ----------------
__global__ void __launch_bounds__(BDIM) k_det_raster(float* __restrict__ out){
    __shared__ __align__(16) unsigned char smemA[16384 + KCAP*8];
    __shared__ float sS2[TK2];
    __shared__ int   sCh[TK2];
    __shared__ int4  sCo[TK2];
    __shared__ unsigned char sV[TK2];
    unsigned*           hist = (unsigned*)smemA;
    unsigned long long* keys = (unsigned long long*)(smemA + 16384);
    int b = blockIdx.x, tid = threadIdx.x, bd = blockDim.x;

    topk_sorted(g_detKey + (size_t)b*NDET, NDET, TK2, hist, keys);

    for (int k = tid; k < TK2; k += bd){
        unsigned long long kk = keys[k];
        int fi   = (int)(~(unsigned)(kk & 0xFFFFFFFFu));
        float s  = u2f((unsigned)(kk >> 32));
        int c = fi / TK1, r = fi % TK1;
        int idx = g_selIdx[(b*NC + c)*TK1 + r];
        float4 bx = g_boxes[(size_t)b*PRI + idx];
        int4 co;
        co.x = (int)rintf(__fmul_rn(bx.x, (float)OGRID));
        co.y = (int)rintf(__fmul_rn(bx.y, (float)OGRID));
        co.z = (int)rintf(__fmul_rn(bx.z, (float)OGRID));
        co.w = (int)rintf(__fmul_rn(bx.w, (float)OGRID));
        sS2[k] = s; sCh[k] = c; sCo[k] = co; sV[k] = (s >= 0.6f) ? 1 : 0;
    }
    __syncthreads();

    for (int cell = tid; cell < OGRID*OGRID; cell += bd){
        int y = cell / OGRID, xp = cell % OGRID;
        float* o = out + ((size_t)b*OGRID*OGRID + cell) * 81;
        for (int ch = 0; ch < 81; ch++) o[ch] = 0.0f;
        for (int k = 0; k < TK2; k++){
            if (sV[k]){
                int4 co = sCo[k];
                if (y >= co.y && y < co.w && xp >= co.x && xp < co.z)
                    o[sCh[k]] = sS2[k];     // ascending k: last writer == max k
            }
        }
    }
}

// ---------------- launch ----------------
extern "C" void kernel_launch(void* const* d_in, const int* in_sizes, int n_in,
                              void* d_out, int out_size){
    const float* x = (const float*)d_in[0];
    float* out = (float*)d_out;
    dim3 g1((PRI + TPRI - 1) / TPRI, BATCH);
    k_decode<<<g1, 128>>>(x);
    k_class<<<BATCH*NC, BDIM>>>();
    k_det_raster<<<BATCH, BDIM>>>(out);
}

// round 7
// speedup vs baseline: 1.6554x; 1.0297x over previous
#include <cuda_runtime.h>
#include <math.h>

#define BATCH 8
#define PRI   24564
#define NC    80        // classes 1..80 (channel slots)
#define CDIM  93
#define TK1   400
#define TK2   200
#define NDET  (NC*TK1)  // 32000
#define OGRID 19
#define NWORD 7         // ceil(400/64)
#define SENT  0x407FFFFFu   // f2u(-1.0f)
#define BDIM  256
#define KCAP  512       // candidate capacity / sort size

// ---------------- scratch (device globals; no allocation allowed) ----------------
__device__ float4       g_boxes[BATCH*PRI];
__device__ unsigned int g_keys[(size_t)BATCH*NC*PRI];    // transformed masked conf, [b][c][p]
__device__ int          g_selIdx[BATCH*NC*TK1];
__device__ unsigned int g_detKey[BATCH*NDET];            // transformed det score per (b, c*400+r)

// order-preserving float<->uint transform (total order, -1 < all positives)
__device__ __forceinline__ unsigned f2u(float f){
    unsigned u = __float_as_uint(f);
    return (u & 0x80000000u) ? ~u : (u | 0x80000000u);
}
__device__ __forceinline__ float u2f(unsigned u){
    return (u & 0x80000000u) ? __uint_as_float(u & 0x7FFFFFFFu) : __uint_as_float(~u);
}

// precise expf even if harness compiles with fast-math
__device__ __forceinline__ float exp_precise(float a){
#if defined(__USE_FAST_MATH__) || defined(__FAST_MATH__)
    return (float)exp((double)a);
#else
    return expf(a);
#endif
}

// ---------------- K1: decode boxes + transpose masked conf into keys ----------------
#define TPRI 32
__global__ void __launch_bounds__(128) k_decode(const float* __restrict__ x){
    __shared__ __align__(16) float tile[TPRI*CDIM];
    int b   = blockIdx.y;
    int pb  = blockIdx.x * TPRI;
    int cnt = min(TPRI, PRI - pb);
    int tid = threadIdx.x, bd = blockDim.x;
    const float* src = x + ((size_t)b*PRI + pb)*CDIM;
    int nv = (cnt*CDIM) >> 2;
    const float4* src4 = (const float4*)src;
    float4* tile4 = (float4*)tile;
    for (int i = tid; i < nv; i += bd) tile4[i] = src4[i];
    __syncthreads();
    if (tid < cnt){
        const float* r = &tile[tid*CDIM];
        float l0=r[0], l1=r[1], l2=r[2], l3=r[3];
        float q0=r[85], q1=r[86], q2=r[87], q3=r[88];
        float v0=r[89], v1=r[90], v2=r[91], v3=r[92];
        float pw  = __fsub_rn(q2,q0), ph = __fsub_rn(q3,q1);
        float pcx = __fmul_rn(0.5f, __fadd_rn(q2,q0));
        float pcy = __fmul_rn(0.5f, __fadd_rn(q3,q1));
        float cx  = __fadd_rn(__fmul_rn(__fmul_rn(l0,pw), v0), pcx);
        float cy  = __fadd_rn(__fmul_rn(__fmul_rn(l1,pw), v1), pcy);  // ref uses pw for cy too
        float w   = __fmul_rn(exp_precise(__fmul_rn(l2,v2)), pw);
        float h   = __fmul_rn(exp_precise(__fmul_rn(l3,v3)), ph);
        float4 bx;
        bx.x = fminf(fmaxf(__fsub_rn(cx, __fmul_rn(0.5f,w)), 0.f), 1.f);
        bx.y = fminf(fmaxf(__fsub_rn(cy, __fmul_rn(0.5f,h)), 0.f), 1.f);
        bx.z = fminf(fmaxf(__fadd_rn(cx, __fmul_rn(0.5f,w)), 0.f), 1.f);
        bx.w = fminf(fmaxf(__fadd_rn(cy, __fmul_rn(0.5f,h)), 0.f), 1.f);
        g_boxes[(size_t)b*PRI + pb + tid] = bx;
    }
    for (int j = tid; j < NC*TPRI; j += bd){
        int c = j >> 5, pl = j & (TPRI-1);
        if (pl < cnt){
            float v = tile[pl*CDIM + 5 + c];
            g_keys[((size_t)(b*NC + c))*PRI + pb + pl] = (v > 0.01f) ? f2u(v) : SENT;
        }
    }
}

// ---------------- bitonic sort (descending) over keys[0..512) ----------------
__device__ void bitonic_desc512(unsigned long long* keys){
    const int tid = threadIdx.x, bd = blockDim.x;
    for (int size = 2; size <= KCAP; size <<= 1){
        for (int stride = size >> 1; stride > 0; stride >>= 1){
            __syncthreads();
            for (int i = tid; i < KCAP; i += bd){
                int j = i ^ stride;
                if (j > i){
                    unsigned long long a = keys[i], b = keys[j];
                    bool up = ((i & size) == 0);
                    if (up ? (a < b) : (a > b)){ keys[i] = b; keys[j] = a; }
                }
            }
        }
    }
    __syncthreads();
}

// ---------------- block-wide exact top-K via threshold probing (no histograms) -------
// N divisible by 4. keys: 512 u64 out; keys[0..K-1] = top-K sorted desc by (value,~index).
__device__ void topk_sorted(const unsigned* __restrict__ g, int N, int K,
                            unsigned long long* keys)
{
    __shared__ int s_c, s_cnt, s_eqbase;
    __shared__ int warpTot[8];
    const int tid = threadIdx.x, bd = BDIM;
    const int wid = tid >> 5, lane = tid & 31;
    const uint4* g4 = (const uint4*)g;
    const int N4 = N >> 2;
    const int target = (K + KCAP) / 2;

    for (int i = tid; i < KCAP; i += bd) keys[i] = 0ULL;
    if (tid == 0){ s_cnt = 0; s_eqbase = 0; }

    // --- probe loop: find T with K <= count(>=T) <= KCAP, or collapse to tie ---
    unsigned lo = 0u, hi = 0xFFFFFFFFu;
    int clo = N, chi = 0;            // counts at lo / hi (chi approximate until probed)
    unsigned Tb = 0u;
    bool found = false;
    for (int iter = 0; iter < 72 && !found && (hi - lo) > 1u; iter++){
        unsigned T;
        if (iter == 0)      T = 0x80000000u;          // f2u(+0.0f)
        else if (iter == 1) T = 0xBF800000u;          // f2u(1.0f)
        else if (iter & 1){                            // interpolate in float space
            double flo = (double)u2f(lo), fhi = (double)u2f(hi);
            double dc  = (double)clo - (double)chi;
            if (isfinite(flo) && isfinite(fhi) && dc > 0.5){
                double ft = fhi - (fhi - flo) * ((double)target - (double)chi) / dc;
                T = f2u((float)ft);
            } else T = lo + ((hi - lo) >> 1);
        } else T = lo + ((hi - lo) >> 1);              // guaranteed-progress bisection
        if (T <= lo) T = lo + 1u;
        if (T > hi)  T = hi;

        if (tid == 0) s_c = 0;
        __syncthreads();
        int cnt = 0;
        for (int i4 = tid; i4 < N4; i4 += bd){
            uint4 v = g4[i4];
            cnt += (v.x >= T) + (v.y >= T) + (v.z >= T) + (v.w >= T);
        }
        #pragma unroll
        for (int o = 16; o; o >>= 1) cnt += __shfl_down_sync(0xFFFFFFFFu, cnt, o);
        if (lane == 0 && cnt) atomicAdd(&s_c, cnt);
        __syncthreads();
        int c = s_c;
        __syncthreads();   // protect s_c from next iteration's reset

        if (c >= K && c <= KCAP){ Tb = T; found = true; }
        else if (c > KCAP){ lo = T; clo = c; }
        else              { hi = T; chi = c; }
    }

    if (found){
        // compact all v >= Tb (ballot-aggregated). UNIFORM trip count.
        for (int base = 0; base < N4; base += bd){
            int i4 = base + tid;
            bool inb = (i4 < N4);
            uint4 v = inb ? g4[i4] : make_uint4(0u,0u,0u,0u);
            #pragma unroll
            for (int c = 0; c < 4; c++){
                unsigned vv = (c==0)?v.x:(c==1)?v.y:(c==2)?v.z:v.w;
                bool pred = inb && (vv >= Tb);
                unsigned ball = __ballot_sync(0xFFFFFFFFu, pred);
                int cntw = __popc(ball);
                int wbase = 0;
                if (lane == 0 && cntw) wbase = atomicAdd(&s_cnt, cntw);
                wbase = __shfl_sync(0xFFFFFFFFu, wbase, 0);
                if (pred){
                    int off = __popc(ball & ((1u << lane) - 1u));
                    unsigned idx = (unsigned)(i4*4 + c);
                    keys[wbase + off] = ((unsigned long long)vv << 32) | (~idx);
                }
            }
        }
        __syncthreads();
        bitonic_desc512(keys);
    } else {
        // tie fallback at T = lo: count(>lo) < K <= count(>=lo)
        const unsigned T = lo;
        for (int base = 0; base < N4; base += bd){
            int i4 = base + tid;
            bool inb = (i4 < N4);
            uint4 v = inb ? g4[i4] : make_uint4(0u,0u,0u,0u);
            #pragma unroll
            for (int c = 0; c < 4; c++){
                unsigned vv = (c==0)?v.x:(c==1)?v.y:(c==2)?v.z:v.w;
                bool pred = inb && (vv > T);
                unsigned ball = __ballot_sync(0xFFFFFFFFu, pred);
                int cntw = __popc(ball);
                int wbase = 0;
                if (lane == 0 && cntw) wbase = atomicAdd(&s_cnt, cntw);
                wbase = __shfl_sync(0xFFFFFFFFu, wbase, 0);
                if (pred){
                    int off = __popc(ball & ((1u << lane) - 1u));
                    unsigned idx = (unsigned)(i4*4 + c);
                    if (wbase + off < KCAP)
                        keys[wbase + off] = ((unsigned long long)vv << 32) | (~idx);
                }
            }
        }
        __syncthreads();
        const int cntAbove = min(s_cnt, KCAP);
        const int need = K - cntAbove;      // > 0 by invariant
        // ordered (lowest index first) pick of `need` elements == T
        for (int base = 0; base < N && s_eqbase < need; base += bd){
            int i = base + tid;
            bool eq = (i < N) && (g[i] == T);
            unsigned ball = __ballot_sync(0xFFFFFFFFu, eq);
            int wpre = __popc(ball & ((1u << lane) - 1u));
            if (lane == 0) warpTot[wid] = __popc(ball);
            __syncthreads();
            int pre = 0;
            for (int w = 0; w < wid; w++) pre += warpTot[w];
            int rank = s_eqbase + pre + wpre;
            if (eq && rank < need && cntAbove + rank < KCAP)
                keys[cntAbove + rank] = ((unsigned long long)T << 32) | (unsigned)(~(unsigned)i);
            __syncthreads();
            if (tid == 0){ int tot = 0; for (int w = 0; w < 8; w++) tot += warpTot[w]; s_eqbase += tot; }
            __syncthreads();
        }
        __syncthreads();
        bitonic_desc512(keys);
    }
}

// IoU > 0.45 test, exact on the boundary band
__device__ __forceinline__ bool iou_gt(const float4& a, float aa, const float4& d, float dd){
    float ix1 = fmaxf(a.x, d.x), iy1 = fmaxf(a.y, d.y);
    float ix2 = fminf(a.z, d.z), iy2 = fminf(a.w, d.w);
    float iw = fmaxf(__fsub_rn(ix2, ix1), 0.0f);
    float ih = fmaxf(__fsub_rn(iy2, iy1), 0.0f);
    float inter = __fmul_rn(iw, ih);
    if (inter <= 0.0f) return false;
    float uni = __fsub_rn(__fadd_rn(aa, dd), inter);
    if (uni <= 0.0f) return false;
    if (inter > 0.46f*uni) return true;
    if (inter < 0.44f*uni) return false;
    return __fdiv_rn(inter, uni) > 0.45f;
}

// ---------------- K2: fused per-(b,c) top-400 + greedy NMS ----------------
#define SMEMA_BYTES 22528   // max(keys 4096, smat 22400)
__global__ void __launch_bounds__(BDIM, 5) k_class(){
    __shared__ __align__(16) unsigned char smemA[SMEMA_BYTES];
    __shared__ float4 sbox[TK1];
    __shared__ float  sarea[TK1];
    __shared__ float  sS[TK1];
    __shared__ unsigned long long skept[NWORD];
    unsigned long long* keys = (unsigned long long*)smemA;
    unsigned long long* smat = (unsigned long long*)smemA;   // overwrites keys after consumption

    int bc = blockIdx.x, b = bc / NC, c = bc % NC;
    int tid = threadIdx.x, bd = blockDim.x, wid = tid >> 5;

    topk_sorted(g_keys + (size_t)bc*PRI, PRI, TK1, keys);

    for (int r = tid; r < TK1; r += bd){
        unsigned long long kk = keys[r];
        int idx  = (int)(~(unsigned)(kk & 0xFFFFFFFFu));
        float sc = u2f((unsigned)(kk >> 32));
        float4 bx = g_boxes[(size_t)b*PRI + idx];
        sbox[r] = bx; sS[r] = sc;
        sarea[r] = __fmul_rn(__fsub_rn(bx.z,bx.x), __fsub_rn(bx.w,bx.y));
        g_selIdx[bc*TK1 + r] = idx;
    }
    __syncthreads();   // keys fully consumed; smat may overwrite

    // lower-triangle suppression bitmatrix: bit (i,j) = iou(i,j) > 0.45, j < i
    for (int t = tid; t < TK1*NWORD; t += bd){
        int i = t / NWORD, w = t - i*NWORD;
        int j0 = w*64, j1 = min(i, j0 + 64);
        unsigned long long word = 0;
        if (j1 > j0){
            float4 a = sbox[i]; float ai = sarea[i];
            for (int j = j0; j < j1; j++){
                if (iou_gt(a, ai, sbox[j], sarea[j])) word |= 1ULL << (j - j0);
            }
        }
        smat[i*NWORD + w] = word;
    }
    __syncthreads();

    // sequential greedy scan; scan-warp varies per block to spread across SMSPs
    int swid = blockIdx.x & 7;
    if (wid == swid){
        int lane = tid & 31;
        unsigned long long keptw = 0;
        unsigned long long row = (lane < NWORD) ? smat[lane] : 0ULL;
        float sc = sS[0];
        for (int i = 0; i < TK1; i++){
            unsigned long long nrow = 0ULL; float nsc = 0.f;
            if (i + 1 < TK1){
                if (lane < NWORD) nrow = smat[(i+1)*NWORD + lane];
                nsc = sS[i+1];
            }
            bool any = __any_sync(0xFFFFFFFFu, (row & keptw) != 0ULL);
            if (sc > 0.01f && !any && lane == (i >> 6)) keptw |= 1ULL << (i & 63);
            row = nrow; sc = nsc;
        }
        if (lane < NWORD) skept[lane] = keptw;
    }
    __syncthreads();

    for (int r = tid; r < TK1; r += bd){
        bool kept = (skept[r >> 6] >> (r & 63)) & 1ULL;
        float sc = kept ? sS[r] : -1.0f;
        g_detKey[(size_t)b*NDET + c*TK1 + r] = f2u(sc);
    }
}

// ---------------- K3: fused per-batch top-200 + rasterize ----------------
__global__ void __launch_bounds__(BDIM) k_det_raster(float* __restrict__ out){
    __shared__ __align__(16) unsigned long long keys[KCAP];
    __shared__ float sS2[TK2];
    __shared__ int   sCh[TK2];
    __shared__ int4  sCo[TK2];
    __shared__ unsigned char sV[TK2];
    int b = blockIdx.x, tid = threadIdx.x, bd = blockDim.x;

    topk_sorted(g_detKey + (size_t)b*NDET, NDET, TK2, keys);

    for (int k = tid; k < TK2; k += bd){
        unsigned long long kk = keys[k];
        int fi   = (int)(~(unsigned)(kk & 0xFFFFFFFFu));
        float s  = u2f((unsigned)(kk >> 32));
        int c = fi / TK1, r = fi % TK1;
        int idx = g_selIdx[(b*NC + c)*TK1 + r];
        float4 bx = g_boxes[(size_t)b*PRI + idx];
        int4 co;
        co.x = (int)rintf(__fmul_rn(bx.x, (float)OGRID));
        co.y = (int)rintf(__fmul_rn(bx.y, (float)OGRID));
        co.z = (int)rintf(__fmul_rn(bx.z, (float)OGRID));
        co.w = (int)rintf(__fmul_rn(bx.w, (float)OGRID));
        sS2[k] = s; sCh[k] = c; sCo[k] = co; sV[k] = (s >= 0.6f) ? 1 : 0;
    }
    __syncthreads();

    for (int cell = tid; cell < OGRID*OGRID; cell += bd){
        int y = cell / OGRID, xp = cell % OGRID;
        float* o = out + ((size_t)b*OGRID*OGRID + cell) * 81;
        for (int ch = 0; ch < 81; ch++) o[ch] = 0.0f;
        for (int k = 0; k < TK2; k++){
            if (sV[k]){
                int4 co = sCo[k];
                if (y >= co.y && y < co.w && xp >= co.x && xp < co.z)
                    o[sCh[k]] = sS2[k];     // ascending k: last writer == max k
            }
        }
    }
}

// ---------------- launch ----------------
extern "C" void kernel_launch(void* const* d_in, const int* in_sizes, int n_in,
                              void* d_out, int out_size){
    const float* x = (const float*)d_in[0];
    float* out = (float*)d_out;
    dim3 g1((PRI + TPRI - 1) / TPRI, BATCH);
    k_decode<<<g1, 128>>>(x);
    k_class<<<BATCH*NC, BDIM>>>();
    k_det_raster<<<BATCH, BDIM>>>(out);
}

// round 8
// speedup vs baseline: 2.2348x; 1.3500x over previous
#include <cuda_runtime.h>
#include <math.h>

#define BATCH 8
#define PRI   24564
#define NC    80        // classes 1..80 (channel slots)
#define CDIM  93
#define TK1   400
#define TK2   200
#define NDET  (NC*TK1)  // 32000
#define OGRID 19
#define NW32  13        // ceil(400/32) 32-bit words per bitmatrix row
#define SENT  0x407FFFFFu   // f2u(-1.0f)
#define BDIM  256
#define KCAP  512       // candidate capacity / sort size

// ---------------- scratch (device globals; no allocation allowed) ----------------
__device__ float4       g_boxes[BATCH*PRI];
__device__ unsigned int g_keys[(size_t)BATCH*NC*PRI];    // transformed masked conf, [b][c][p]
__device__ int          g_selIdx[BATCH*NC*TK1];
__device__ unsigned int g_detKey[BATCH*NDET];            // transformed det score per (b, c*400+r)

// order-preserving float<->uint transform (total order, -1 < all positives)
__device__ __forceinline__ unsigned f2u(float f){
    unsigned u = __float_as_uint(f);
    return (u & 0x80000000u) ? ~u : (u | 0x80000000u);
}
__device__ __forceinline__ float u2f(unsigned u){
    return (u & 0x80000000u) ? __uint_as_float(u & 0x7FFFFFFFu) : __uint_as_float(~u);
}

// precise expf even if harness compiles with fast-math
__device__ __forceinline__ float exp_precise(float a){
#if defined(__USE_FAST_MATH__) || defined(__FAST_MATH__)
    return (float)exp((double)a);
#else
    return expf(a);
#endif
}

// ---------------- K1: decode boxes + transpose masked conf into keys ----------------
#define TPRI 32
__global__ void __launch_bounds__(128) k_decode(const float* __restrict__ x){
    __shared__ __align__(16) float tile[TPRI*CDIM];
    int b   = blockIdx.y;
    int pb  = blockIdx.x * TPRI;
    int cnt = min(TPRI, PRI - pb);
    int tid = threadIdx.x, bd = blockDim.x;
    const float* src = x + ((size_t)b*PRI + pb)*CDIM;
    int nv = (cnt*CDIM) >> 2;
    const float4* src4 = (const float4*)src;
    float4* tile4 = (float4*)tile;
    for (int i = tid; i < nv; i += bd) tile4[i] = src4[i];
    __syncthreads();
    if (tid < cnt){
        const float* r = &tile[tid*CDIM];
        float l0=r[0], l1=r[1], l2=r[2], l3=r[3];
        float q0=r[85], q1=r[86], q2=r[87], q3=r[88];
        float v0=r[89], v1=r[90], v2=r[91], v3=r[92];
        float pw  = __fsub_rn(q2,q0), ph = __fsub_rn(q3,q1);
        float pcx = __fmul_rn(0.5f, __fadd_rn(q2,q0));
        float pcy = __fmul_rn(0.5f, __fadd_rn(q3,q1));
        float cx  = __fadd_rn(__fmul_rn(__fmul_rn(l0,pw), v0), pcx);
        float cy  = __fadd_rn(__fmul_rn(__fmul_rn(l1,pw), v1), pcy);  // ref uses pw for cy too
        float w   = __fmul_rn(exp_precise(__fmul_rn(l2,v2)), pw);
        float h   = __fmul_rn(exp_precise(__fmul_rn(l3,v3)), ph);
        float4 bx;
        bx.x = fminf(fmaxf(__fsub_rn(cx, __fmul_rn(0.5f,w)), 0.f), 1.f);
        bx.y = fminf(fmaxf(__fsub_rn(cy, __fmul_rn(0.5f,h)), 0.f), 1.f);
        bx.z = fminf(fmaxf(__fadd_rn(cx, __fmul_rn(0.5f,w)), 0.f), 1.f);
        bx.w = fminf(fmaxf(__fadd_rn(cy, __fmul_rn(0.5f,h)), 0.f), 1.f);
        g_boxes[(size_t)b*PRI + pb + tid] = bx;
    }
    for (int j = tid; j < NC*TPRI; j += bd){
        int c = j >> 5, pl = j & (TPRI-1);
        if (pl < cnt){
            float v = tile[pl*CDIM + 5 + c];
            g_keys[((size_t)(b*NC + c))*PRI + pb + pl] = (v > 0.01f) ? f2u(v) : SENT;
        }
    }
}

// ---------------- bitonic sort (descending) over keys[0..512) ----------------
__device__ void bitonic_desc512(unsigned long long* keys){
    const int tid = threadIdx.x, bd = blockDim.x;
    for (int size = 2; size <= KCAP; size <<= 1){
        for (int stride = size >> 1; stride > 0; stride >>= 1){
            __syncthreads();
            for (int i = tid; i < KCAP; i += bd){
                int j = i ^ stride;
                if (j > i){
                    unsigned long long a = keys[i], b = keys[j];
                    bool up = ((i & size) == 0);
                    if (up ? (a < b) : (a > b)){ keys[i] = b; keys[j] = a; }
                }
            }
        }
    }
    __syncthreads();
}

// ---------------- block-wide exact top-K via threshold probing (no histograms) -------
// N divisible by 4. keys: 512 u64 out; keys[0..K-1] = top-K sorted desc by (value,~index).
__device__ void topk_sorted(const unsigned* __restrict__ g, int N, int K,
                            unsigned long long* keys)
{
    __shared__ int s_c, s_cnt, s_eqbase;
    __shared__ int warpTot[8];
    const int tid = threadIdx.x, bd = BDIM;
    const int wid = tid >> 5, lane = tid & 31;
    const uint4* g4 = (const uint4*)g;
    const int N4 = N >> 2;
    const int target = (K + KCAP) / 2;

    for (int i = tid; i < KCAP; i += bd) keys[i] = 0ULL;
    if (tid == 0){ s_cnt = 0; s_eqbase = 0; }

    // --- probe loop: find T with K <= count(>=T) <= KCAP, or collapse to tie ---
    unsigned lo = 0u, hi = 0xFFFFFFFFu;
    int clo = N, chi = 0;            // counts at lo / hi (chi approximate until probed)
    unsigned Tb = 0u;
    bool found = false;
    for (int iter = 0; iter < 72 && !found && (hi - lo) > 1u; iter++){
        unsigned T;
        if (iter == 0)      T = 0x80000000u;          // f2u(+0.0f)
        else if (iter == 1) T = 0xBF800000u;          // f2u(1.0f)
        else if (iter & 1){                            // interpolate in float space
            double flo = (double)u2f(lo), fhi = (double)u2f(hi);
            double dc  = (double)clo - (double)chi;
            if (isfinite(flo) && isfinite(fhi) && dc > 0.5){
                double ft = fhi - (fhi - flo) * ((double)target - (double)chi) / dc;
                T = f2u((float)ft);
            } else T = lo + ((hi - lo) >> 1);
        } else T = lo + ((hi - lo) >> 1);              // guaranteed-progress bisection
        if (T <= lo) T = lo + 1u;
        if (T > hi)  T = hi;

        if (tid == 0) s_c = 0;
        __syncthreads();
        int cnt = 0;
        for (int i4 = tid; i4 < N4; i4 += bd){
            uint4 v = g4[i4];
            cnt += (v.x >= T) + (v.y >= T) + (v.z >= T) + (v.w >= T);
        }
        #pragma unroll
        for (int o = 16; o; o >>= 1) cnt += __shfl_down_sync(0xFFFFFFFFu, cnt, o);
        if (lane == 0 && cnt) atomicAdd(&s_c, cnt);
        __syncthreads();
        int c = s_c;
        __syncthreads();   // protect s_c from next iteration's reset

        if (c >= K && c <= KCAP){ Tb = T; found = true; }
        else if (c > KCAP){ lo = T; clo = c; }
        else              { hi = T; chi = c; }
    }

    if (found){
        // compact all v >= Tb (ballot-aggregated). UNIFORM trip count.
        for (int base = 0; base < N4; base += bd){
            int i4 = base + tid;
            bool inb = (i4 < N4);
            uint4 v = inb ? g4[i4] : make_uint4(0u,0u,0u,0u);
            #pragma unroll
            for (int c = 0; c < 4; c++){
                unsigned vv = (c==0)?v.x:(c==1)?v.y:(c==2)?v.z:v.w;
                bool pred = inb && (vv >= Tb);
                unsigned ball = __ballot_sync(0xFFFFFFFFu, pred);
                int cntw = __popc(ball);
                int wbase = 0;
                if (lane == 0 && cntw) wbase = atomicAdd(&s_cnt, cntw);
                wbase = __shfl_sync(0xFFFFFFFFu, wbase, 0);
                if (pred){
                    int off = __popc(ball & ((1u << lane) - 1u));
                    unsigned idx = (unsigned)(i4*4 + c);
                    keys[wbase + off] = ((unsigned long long)vv << 32) | (~idx);
                }
            }
        }
        __syncthreads();
        bitonic_desc512(keys);
    } else {
        // tie fallback at T = lo: count(>lo) < K <= count(>=lo)
        const unsigned T = lo;
        for (int base = 0; base < N4; base += bd){
            int i4 = base + tid;
            bool inb = (i4 < N4);
            uint4 v = inb ? g4[i4] : make_uint4(0u,0u,0u,0u);
            #pragma unroll
            for (int c = 0; c < 4; c++){
                unsigned vv = (c==0)?v.x:(c==1)?v.y:(c==2)?v.z:v.w;
                bool pred = inb && (vv > T);
                unsigned ball = __ballot_sync(0xFFFFFFFFu, pred);
                int cntw = __popc(ball);
                int wbase = 0;
                if (lane == 0 && cntw) wbase = atomicAdd(&s_cnt, cntw);
                wbase = __shfl_sync(0xFFFFFFFFu, wbase, 0);
                if (pred){
                    int off = __popc(ball & ((1u << lane) - 1u));
                    unsigned idx = (unsigned)(i4*4 + c);
                    if (wbase + off < KCAP)
                        keys[wbase + off] = ((unsigned long long)vv << 32) | (~idx);
                }
            }
        }
        __syncthreads();
        const int cntAbove = min(s_cnt, KCAP);
        const int need = K - cntAbove;      // > 0 by invariant
        // ordered (lowest index first) pick of `need` elements == T
        for (int base = 0; base < N && s_eqbase < need; base += bd){
            int i = base + tid;
            bool eq = (i < N) && (g[i] == T);
            unsigned ball = __ballot_sync(0xFFFFFFFFu, eq);
            int wpre = __popc(ball & ((1u << lane) - 1u));
            if (lane == 0) warpTot[wid] = __popc(ball);
            __syncthreads();
            int pre = 0;
            for (int w = 0; w < wid; w++) pre += warpTot[w];
            int rank = s_eqbase + pre + wpre;
            if (eq && rank < need && cntAbove + rank < KCAP)
                keys[cntAbove + rank] = ((unsigned long long)T << 32) | (unsigned)(~(unsigned)i);
            __syncthreads();
            if (tid == 0){ int tot = 0; for (int w = 0; w < 8; w++) tot += warpTot[w]; s_eqbase += tot; }
            __syncthreads();
        }
        __syncthreads();
        bitonic_desc512(keys);
    }
}

// IoU > 0.45 test, exact on the boundary band
__device__ __forceinline__ bool iou_gt(const float4& a, float aa, const float4& d, float dd){
    float ix1 = fmaxf(a.x, d.x), iy1 = fmaxf(a.y, d.y);
    float ix2 = fminf(a.z, d.z), iy2 = fminf(a.w, d.w);
    float iw = fmaxf(__fsub_rn(ix2, ix1), 0.0f);
    float ih = fmaxf(__fsub_rn(iy2, iy1), 0.0f);
    float inter = __fmul_rn(iw, ih);
    if (inter <= 0.0f) return false;
    float uni = __fsub_rn(__fadd_rn(aa, dd), inter);
    if (uni <= 0.0f) return false;
    if (inter > 0.46f*uni) return true;
    if (inter < 0.44f*uni) return false;
    return __fdiv_rn(inter, uni) > 0.45f;
}

// ---------------- K2: fused per-(b,c) top-400 + greedy NMS ----------------
#define SMEMA_BYTES 22528   // max(keys 4096, smat 400*13*4 = 20800)
__global__ void __launch_bounds__(BDIM, 5) k_class(){
    __shared__ __align__(16) unsigned char smemA[SMEMA_BYTES];
    __shared__ float4 sbox[TK1];
    __shared__ float  sarea[TK1];
    __shared__ float  sS[TK1];
    __shared__ unsigned skept[NW32];
    unsigned long long* keys = (unsigned long long*)smemA;
    unsigned*           smat = (unsigned*)smemA;   // overwrites keys after consumption

    int bc = blockIdx.x, b = bc / NC, c = bc % NC;
    int tid = threadIdx.x, bd = blockDim.x, wid = tid >> 5, lane = tid & 31;

    topk_sorted(g_keys + (size_t)bc*PRI, PRI, TK1, keys);

    for (int r = tid; r < TK1; r += bd){
        unsigned long long kk = keys[r];
        int idx  = (int)(~(unsigned)(kk & 0xFFFFFFFFu));
        float sc = u2f((unsigned)(kk >> 32));
        float4 bx = g_boxes[(size_t)b*PRI + idx];
        sbox[r] = bx; sS[r] = sc;
        sarea[r] = __fmul_rn(__fsub_rn(bx.z,bx.x), __fsub_rn(bx.w,bx.y));
        g_selIdx[bc*TK1 + r] = idx;
    }
    __syncthreads();   // keys fully consumed; smat may overwrite

    // lane-parallel suppression bitmatrix: warp per row group, lanes sweep j.
    // smat[i][wdx] bit L = iou(i, 32*wdx+L) > 0.45, defined for j < i.
    // Words wdx >= ceil(i/32) are left unwritten: the greedy scan ANDs them with
    // kept bits that are still 0 at iteration i, so garbage is harmless.
    for (int i = wid; i < TK1; i += 8){
        float4 a = sbox[i]; float aa = sarea[i];
        int nw = (i + 31) >> 5;
        for (int wdx = 0; wdx < nw; wdx++){
            int j = (wdx << 5) + lane;
            bool gt = (j < i) && iou_gt(a, aa, sbox[j], sarea[j]);
            unsigned m = __ballot_sync(0xFFFFFFFFu, gt);
            if (lane == 0) smat[i*NW32 + wdx] = m;
        }
    }
    __syncthreads();

    // sequential greedy scan; scan-warp varies per block to spread across SMSPs
    int swid = blockIdx.x & 7;
    if (wid == swid){
        unsigned kept32 = 0;   // lane L holds kept bits for j in [32L, 32L+32)
        unsigned row = (lane < NW32) ? smat[lane] : 0u;
        float sc = sS[0];
        for (int i = 0; i < TK1; i++){
            unsigned nrow = 0u; float nsc = 0.f;
            if (i + 1 < TK1){
                if (lane < NW32) nrow = smat[(i+1)*NW32 + lane];
                nsc = sS[i+1];
            }
            bool any = __any_sync(0xFFFFFFFFu, (row & kept32) != 0u);
            if (sc > 0.01f && !any && lane == (i >> 5)) kept32 |= 1u << (i & 31);
            row = nrow; sc = nsc;
        }
        if (lane < NW32) skept[lane] = kept32;
    }
    __syncthreads();

    for (int r = tid; r < TK1; r += bd){
        bool kept = (skept[r >> 5] >> (r & 31)) & 1u;
        float sc = kept ? sS[r] : -1.0f;
        g_detKey[(size_t)b*NDET + c*TK1 + r] = f2u(sc);
    }
}

// ---------------- K3: fused per-batch top-200 + rasterize ----------------
__global__ void __launch_bounds__(BDIM) k_det_raster(float* __restrict__ out){
    __shared__ __align__(16) unsigned long long keys[KCAP];
    __shared__ float sS2[TK2];
    __shared__ int   sCh[TK2];
    __shared__ int4  sCo[TK2];
    __shared__ unsigned char sV[TK2];
    int b = blockIdx.x, tid = threadIdx.x, bd = blockDim.x;

    topk_sorted(g_detKey + (size_t)b*NDET, NDET, TK2, keys);

    for (int k = tid; k < TK2; k += bd){
        unsigned long long kk = keys[k];
        int fi   = (int)(~(unsigned)(kk & 0xFFFFFFFFu));
        float s  = u2f((unsigned)(kk >> 32));
        int c = fi / TK1, r = fi % TK1;
        int idx = g_selIdx[(b*NC + c)*TK1 + r];
        float4 bx = g_boxes[(size_t)b*PRI + idx];
        int4 co;
        co.x = (int)rintf(__fmul_rn(bx.x, (float)OGRID));
        co.y = (int)rintf(__fmul_rn(bx.y, (float)OGRID));
        co.z = (int)rintf(__fmul_rn(bx.z, (float)OGRID));
        co.w = (int)rintf(__fmul_rn(bx.w, (float)OGRID));
        sS2[k] = s; sCh[k] = c; sCo[k] = co; sV[k] = (s >= 0.6f) ? 1 : 0;
    }
    __syncthreads();

    for (int cell = tid; cell < OGRID*OGRID; cell += bd){
        int y = cell / OGRID, xp = cell % OGRID;
        float* o = out + ((size_t)b*OGRID*OGRID + cell) * 81;
        for (int ch = 0; ch < 81; ch++) o[ch] = 0.0f;
        for (int k = 0; k < TK2; k++){
            if (sV[k]){
                int4 co = sCo[k];
                if (y >= co.y && y < co.w && xp >= co.x && xp < co.z)
                    o[sCh[k]] = sS2[k];     // ascending k: last writer == max k
            }
        }
    }
}

// ---------------- launch ----------------
extern "C" void kernel_launch(void* const* d_in, const int* in_sizes, int n_in,
                              void* d_out, int out_size){
    const float* x = (const float*)d_in[0];
    float* out = (float*)d_out;
    dim3 g1((PRI + TPRI - 1) / TPRI, BATCH);
    k_decode<<<g1, 128>>>(x);
    k_class<<<BATCH*NC, BDIM>>>();
    k_det_raster<<<BATCH, BDIM>>>(out);
}

// round 9
// speedup vs baseline: 2.2883x; 1.0240x over previous
#include <cuda_runtime.h>
#include <math.h>

#define BATCH 8
#define PRI   24564
#define NC    80        // classes 1..80 (channel slots)
#define CDIM  93
#define TK1   400
#define TK2   200
#define NDET  (NC*TK1)  // 32000
#define OGRID 19
#define NW32  13        // ceil(400/32) 32-bit words per bitmatrix row
#define SENT  0x407FFFFFu   // f2u(-1.0f)
#define BDIM  256
#define KCAP  512       // candidate capacity / sort size

// ---------------- scratch (device globals; no allocation allowed) ----------------
__device__ float4       g_boxes[BATCH*PRI];
__device__ unsigned int g_keys[(size_t)BATCH*NC*PRI];    // transformed masked conf, [b][c][p]
__device__ int          g_selIdx[BATCH*NC*TK1];
__device__ unsigned int g_detKey[BATCH*NDET];            // transformed det score per (b, c*400+r)

// order-preserving float<->uint transform (total order, -1 < all positives)
__device__ __forceinline__ unsigned f2u(float f){
    unsigned u = __float_as_uint(f);
    return (u & 0x80000000u) ? ~u : (u | 0x80000000u);
}
__device__ __forceinline__ float u2f(unsigned u){
    return (u & 0x80000000u) ? __uint_as_float(u & 0x7FFFFFFFu) : __uint_as_float(~u);
}

// precise expf even if harness compiles with fast-math
__device__ __forceinline__ float exp_precise(float a){
#if defined(__USE_FAST_MATH__) || defined(__FAST_MATH__)
    return (float)exp((double)a);
#else
    return expf(a);
#endif
}

// ---------------- K1: decode boxes + transpose masked conf into keys ----------------
#define TPRI 32
__global__ void __launch_bounds__(128) k_decode(const float* __restrict__ x){
    __shared__ __align__(16) float tile[TPRI*CDIM];
    int b   = blockIdx.y;
    int pb  = blockIdx.x * TPRI;
    int cnt = min(TPRI, PRI - pb);
    int tid = threadIdx.x, bd = blockDim.x;
    const float* src = x + ((size_t)b*PRI + pb)*CDIM;
    int nv = (cnt*CDIM) >> 2;
    const float4* src4 = (const float4*)src;
    float4* tile4 = (float4*)tile;
    for (int i = tid; i < nv; i += bd) tile4[i] = src4[i];
    __syncthreads();
    if (tid < cnt){
        const float* r = &tile[tid*CDIM];
        float l0=r[0], l1=r[1], l2=r[2], l3=r[3];
        float q0=r[85], q1=r[86], q2=r[87], q3=r[88];
        float v0=r[89], v1=r[90], v2=r[91], v3=r[92];
        float pw  = __fsub_rn(q2,q0), ph = __fsub_rn(q3,q1);
        float pcx = __fmul_rn(0.5f, __fadd_rn(q2,q0));
        float pcy = __fmul_rn(0.5f, __fadd_rn(q3,q1));
        float cx  = __fadd_rn(__fmul_rn(__fmul_rn(l0,pw), v0), pcx);
        float cy  = __fadd_rn(__fmul_rn(__fmul_rn(l1,pw), v1), pcy);  // ref uses pw for cy too
        float w   = __fmul_rn(exp_precise(__fmul_rn(l2,v2)), pw);
        float h   = __fmul_rn(exp_precise(__fmul_rn(l3,v3)), ph);
        float4 bx;
        bx.x = fminf(fmaxf(__fsub_rn(cx, __fmul_rn(0.5f,w)), 0.f), 1.f);
        bx.y = fminf(fmaxf(__fsub_rn(cy, __fmul_rn(0.5f,h)), 0.f), 1.f);
        bx.z = fminf(fmaxf(__fadd_rn(cx, __fmul_rn(0.5f,w)), 0.f), 1.f);
        bx.w = fminf(fmaxf(__fadd_rn(cy, __fmul_rn(0.5f,h)), 0.f), 1.f);
        g_boxes[(size_t)b*PRI + pb + tid] = bx;
    }
    for (int j = tid; j < NC*TPRI; j += bd){
        int c = j >> 5, pl = j & (TPRI-1);
        if (pl < cnt){
            float v = tile[pl*CDIM + 5 + c];
            g_keys[((size_t)(b*NC + c))*PRI + pb + pl] = (v > 0.01f) ? f2u(v) : SENT;
        }
    }
}

// ---------------- bitonic sort (descending) over keys[0..512) ----------------
__device__ void bitonic_desc512(unsigned long long* keys){
    const int tid = threadIdx.x, bd = blockDim.x;
    for (int size = 2; size <= KCAP; size <<= 1){
        for (int stride = size >> 1; stride > 0; stride >>= 1){
            __syncthreads();
            for (int i = tid; i < KCAP; i += bd){
                int j = i ^ stride;
                if (j > i){
                    unsigned long long a = keys[i], b = keys[j];
                    bool up = ((i & size) == 0);
                    if (up ? (a < b) : (a > b)){ keys[i] = b; keys[j] = a; }
                }
            }
        }
    }
    __syncthreads();
}

// ---------------- block-wide exact top-K via threshold probing (no histograms) -------
// N divisible by 4. keys: 512 u64 out; keys[0..K-1] = top-K sorted desc by (value,~index).
__device__ void topk_sorted(const unsigned* __restrict__ g, int N, int K,
                            unsigned long long* keys)
{
    __shared__ int s_c, s_cnt, s_eqbase;
    __shared__ int warpTot[8];
    const int tid = threadIdx.x, bd = BDIM;
    const int wid = tid >> 5, lane = tid & 31;
    const uint4* g4 = (const uint4*)g;
    const int N4 = N >> 2;
    const int target = (K + KCAP) / 2;

    for (int i = tid; i < KCAP; i += bd) keys[i] = 0ULL;
    if (tid == 0){ s_cnt = 0; s_eqbase = 0; }

    // --- probe loop: find T with K <= count(>=T) <= KCAP, or collapse to tie ---
    // Schedule: seeds, then float-interp, uint-rank-interp, and (from iter 4)
    // alternating bisection/rank-interp; T clamped to [lo+1, hi-1] so the
    // window shrinks strictly every probe (bisection bound => termination).
    unsigned lo = 0u, hi = 0xFFFFFFFFu;
    int clo = N, chi = 0;
    unsigned Tb = 0u;
    bool found = false;
    for (int iter = 0; iter < 140 && !found && (hi - lo) > 1u; iter++){
        unsigned T;
        if (iter == 0)      T = 0x80000000u;          // f2u(+0.0f)
        else if (iter == 1) T = 0xBF800000u;          // f2u(1.0f)
        else if (iter == 2){                           // float-space interpolation
            double flo = (double)u2f(lo), fhi = (double)u2f(hi);
            double dc  = (double)clo - (double)chi;
            if (isfinite(flo) && isfinite(fhi) && dc > 0.5){
                double ft = fhi - (fhi - flo) * ((double)target - (double)chi) / dc;
                T = f2u((float)ft);
            } else T = lo + ((hi - lo) >> 1);
        } else if ((iter == 3) || (iter & 1)){         // uint rank interpolation
            double dc = (double)clo - (double)chi;
            if (dc > 0.5){
                double frac = ((double)clo - (double)target) / dc;
                if (frac < 0.0) frac = 0.0;
                if (frac > 1.0) frac = 1.0;
                T = lo + (unsigned)((double)(hi - lo) * frac);
            } else T = lo + ((hi - lo) >> 1);
        } else T = lo + ((hi - lo) >> 1);              // bisection
        if (T <= lo) T = lo + 1u;
        if (T >= hi) T = hi - 1u;

        if (tid == 0) s_c = 0;
        __syncthreads();
        int cnt = 0;
        for (int i4 = tid; i4 < N4; i4 += bd){
            uint4 v = g4[i4];
            cnt += (v.x >= T) + (v.y >= T) + (v.z >= T) + (v.w >= T);
        }
        #pragma unroll
        for (int o = 16; o; o >>= 1) cnt += __shfl_down_sync(0xFFFFFFFFu, cnt, o);
        if (lane == 0 && cnt) atomicAdd(&s_c, cnt);
        __syncthreads();
        int c = s_c;
        __syncthreads();   // protect s_c from next iteration's reset

        if (c >= K && c <= KCAP){ Tb = T; found = true; }
        else if (c > KCAP){ lo = T; clo = c; }
        else              { hi = T; chi = c; }
    }

    if (found){
        // compact all v >= Tb (ballot-aggregated). UNIFORM trip count.
        for (int base = 0; base < N4; base += bd){
            int i4 = base + tid;
            bool inb = (i4 < N4);
            uint4 v = inb ? g4[i4] : make_uint4(0u,0u,0u,0u);
            #pragma unroll
            for (int c = 0; c < 4; c++){
                unsigned vv = (c==0)?v.x:(c==1)?v.y:(c==2)?v.z:v.w;
                bool pred = inb && (vv >= Tb);
                unsigned ball = __ballot_sync(0xFFFFFFFFu, pred);
                int cntw = __popc(ball);
                int wbase = 0;
                if (lane == 0 && cntw) wbase = atomicAdd(&s_cnt, cntw);
                wbase = __shfl_sync(0xFFFFFFFFu, wbase, 0);
                if (pred){
                    int off = __popc(ball & ((1u << lane) - 1u));
                    unsigned idx = (unsigned)(i4*4 + c);
                    keys[wbase + off] = ((unsigned long long)vv << 32) | (~idx);
                }
            }
        }
        __syncthreads();
        bitonic_desc512(keys);
    } else {
        // tie fallback at T = lo: count(>lo) < K <= count(>=lo)
        const unsigned T = lo;
        for (int base = 0; base < N4; base += bd){
            int i4 = base + tid;
            bool inb = (i4 < N4);
            uint4 v = inb ? g4[i4] : make_uint4(0u,0u,0u,0u);
            #pragma unroll
            for (int c = 0; c < 4; c++){
                unsigned vv = (c==0)?v.x:(c==1)?v.y:(c==2)?v.z:v.w;
                bool pred = inb && (vv > T);
                unsigned ball = __ballot_sync(0xFFFFFFFFu, pred);
                int cntw = __popc(ball);
                int wbase = 0;
                if (lane == 0 && cntw) wbase = atomicAdd(&s_cnt, cntw);
                wbase = __shfl_sync(0xFFFFFFFFu, wbase, 0);
                if (pred){
                    int off = __popc(ball & ((1u << lane) - 1u));
                    unsigned idx = (unsigned)(i4*4 + c);
                    if (wbase + off < KCAP)
                        keys[wbase + off] = ((unsigned long long)vv << 32) | (~idx);
                }
            }
        }
        __syncthreads();
        const int cntAbove = min(s_cnt, KCAP);
        const int need = K - cntAbove;      // > 0 by invariant
        // ordered (lowest index first) pick of `need` elements == T
        for (int base = 0; base < N && s_eqbase < need; base += bd){
            int i = base + tid;
            bool eq = (i < N) && (g[i] == T);
            unsigned ball = __ballot_sync(0xFFFFFFFFu, eq);
            int wpre = __popc(ball & ((1u << lane) - 1u));
            if (lane == 0) warpTot[wid] = __popc(ball);
            __syncthreads();
            int pre = 0;
            for (int w = 0; w < wid; w++) pre += warpTot[w];
            int rank = s_eqbase + pre + wpre;
            if (eq && rank < need && cntAbove + rank < KCAP)
                keys[cntAbove + rank] = ((unsigned long long)T << 32) | (unsigned)(~(unsigned)i);
            __syncthreads();
            if (tid == 0){ int tot = 0; for (int w = 0; w < 8; w++) tot += warpTot[w]; s_eqbase += tot; }
            __syncthreads();
        }
        __syncthreads();
        bitonic_desc512(keys);
    }
}

// IoU > 0.45 test, exact on the boundary band
__device__ __forceinline__ bool iou_gt(const float4& a, float aa, const float4& d, float dd){
    float ix1 = fmaxf(a.x, d.x), iy1 = fmaxf(a.y, d.y);
    float ix2 = fminf(a.z, d.z), iy2 = fminf(a.w, d.w);
    float iw = fmaxf(__fsub_rn(ix2, ix1), 0.0f);
    float ih = fmaxf(__fsub_rn(iy2, iy1), 0.0f);
    float inter = __fmul_rn(iw, ih);
    if (inter <= 0.0f) return false;
    float uni = __fsub_rn(__fadd_rn(aa, dd), inter);
    if (uni <= 0.0f) return false;
    if (inter > 0.46f*uni) return true;
    if (inter < 0.44f*uni) return false;
    return __fdiv_rn(inter, uni) > 0.45f;
}

// ---------------- K2: fused per-(b,c) top-400 + greedy NMS ----------------
#define SMEMA_BYTES 22528   // max(keys 4096, smat 400*13*4 = 20800)
__global__ void __launch_bounds__(BDIM, 5) k_class(){
    __shared__ __align__(16) unsigned char smemA[SMEMA_BYTES];
    __shared__ float4 sbox[TK1];
    __shared__ float  sarea[TK1];
    __shared__ float  sS[TK1];
    __shared__ unsigned skept[NW32];
    unsigned long long* keys = (unsigned long long*)smemA;
    unsigned*           smat = (unsigned*)smemA;   // overwrites keys after consumption

    int bc = blockIdx.x, b = bc / NC, c = bc % NC;
    int tid = threadIdx.x, bd = blockDim.x, wid = tid >> 5, lane = tid & 31;

    topk_sorted(g_keys + (size_t)bc*PRI, PRI, TK1, keys);

    for (int r = tid; r < TK1; r += bd){
        unsigned long long kk = keys[r];
        int idx  = (int)(~(unsigned)(kk & 0xFFFFFFFFu));
        float sc = u2f((unsigned)(kk >> 32));
        float4 bx = g_boxes[(size_t)b*PRI + idx];
        sbox[r] = bx; sS[r] = sc;
        sarea[r] = __fmul_rn(__fsub_rn(bx.z,bx.x), __fsub_rn(bx.w,bx.y));
        g_selIdx[bc*TK1 + r] = idx;
    }
    __syncthreads();   // keys fully consumed; smat may overwrite

    // transposed, task-balanced suppression bitmatrix.
    // task = (wdx = j-window, ichunk = i-chunk), ichunk >= wdx; 91 tasks over 8 warps.
    // lanes hold the 32 j-boxes of the window in registers; sbox[i]/sarea[i] are
    // broadcast LDS. ballot produces smat[i][wdx] directly; lane (i&31) stores.
    // Words wdx > i>>5 stay unwritten: greedy scan ANDs them with kept bits that
    // are still 0 at iteration i, so garbage is harmless.
    for (int t = wid; t < 91; t += 8){
        int wdx = 0, rem = t;
        while (rem >= NW32 - wdx){ rem -= NW32 - wdx; wdx++; }
        int ichunk = wdx + rem;
        int jb = wdx << 5, ib = ichunk << 5;
        int jj = jb + lane;
        int jjc = min(jj, TK1 - 1);
        float4 jb4 = sbox[jjc]; float ja = sarea[jjc];
        int imax = min(32, TK1 - ib);
        for (int ii = 0; ii < imax; ii++){
            int i = ib + ii;
            float4 a = sbox[i]; float aa = sarea[i];   // broadcast
            bool gt = (jj < i) && iou_gt(a, aa, jb4, ja);
            unsigned m = __ballot_sync(0xFFFFFFFFu, gt);
            if (lane == ii) smat[i*NW32 + wdx] = m;
        }
    }
    __syncthreads();

    // sequential greedy scan; scan-warp varies per block to spread across SMSPs
    int swid = blockIdx.x & 7;
    if (wid == swid){
        unsigned kept32 = 0;   // lane L holds kept bits for j in [32L, 32L+32)
        unsigned row = (lane < NW32) ? smat[lane] : 0u;
        float sc = sS[0];
        for (int i = 0; i < TK1; i++){
            unsigned nrow = 0u; float nsc = 0.f;
            if (i + 1 < TK1){
                if (lane < NW32) nrow = smat[(i+1)*NW32 + lane];
                nsc = sS[i+1];
            }
            bool any = __any_sync(0xFFFFFFFFu, (row & kept32) != 0u);
            if (sc > 0.01f && !any && lane == (i >> 5)) kept32 |= 1u << (i & 31);
            row = nrow; sc = nsc;
        }
        if (lane < NW32) skept[lane] = kept32;
    }
    __syncthreads();

    for (int r = tid; r < TK1; r += bd){
        bool kept = (skept[r >> 5] >> (r & 31)) & 1u;
        float sc = kept ? sS[r] : -1.0f;
        g_detKey[(size_t)b*NDET + c*TK1 + r] = f2u(sc);
    }
}

// ---------------- K3: fused per-batch top-200 + rasterize ----------------
__global__ void __launch_bounds__(BDIM) k_det_raster(float* __restrict__ out){
    __shared__ __align__(16) unsigned long long keys[KCAP];
    __shared__ float sS2[TK2];
    __shared__ int   sCh[TK2];
    __shared__ int4  sCo[TK2];
    __shared__ unsigned char sV[TK2];
    int b = blockIdx.x, tid = threadIdx.x, bd = blockDim.x;

    topk_sorted(g_detKey + (size_t)b*NDET, NDET, TK2, keys);

    for (int k = tid; k < TK2; k += bd){
        unsigned long long kk = keys[k];
        int fi   = (int)(~(unsigned)(kk & 0xFFFFFFFFu));
        float s  = u2f((unsigned)(kk >> 32));
        int c = fi / TK1, r = fi % TK1;
        int idx = g_selIdx[(b*NC + c)*TK1 + r];
        float4 bx = g_boxes[(size_t)b*PRI + idx];
        int4 co;
        co.x = (int)rintf(__fmul_rn(bx.x, (float)OGRID));
        co.y = (int)rintf(__fmul_rn(bx.y, (float)OGRID));
        co.z = (int)rintf(__fmul_rn(bx.z, (float)OGRID));
        co.w = (int)rintf(__fmul_rn(bx.w, (float)OGRID));
        sS2[k] = s; sCh[k] = c; sCo[k] = co; sV[k] = (s >= 0.6f) ? 1 : 0;
    }
    __syncthreads();

    for (int cell = tid; cell < OGRID*OGRID; cell += bd){
        int y = cell / OGRID, xp = cell % OGRID;
        float* o = out + ((size_t)b*OGRID*OGRID + cell) * 81;
        for (int ch = 0; ch < 81; ch++) o[ch] = 0.0f;
        for (int k = 0; k < TK2; k++){
            if (sV[k]){
                int4 co = sCo[k];
                if (y >= co.y && y < co.w && xp >= co.x && xp < co.z)
                    o[sCh[k]] = sS2[k];     // ascending k: last writer == max k
            }
        }
    }
}

// ---------------- launch ----------------
extern "C" void kernel_launch(void* const* d_in, const int* in_sizes, int n_in,
                              void* d_out, int out_size){
    const float* x = (const float*)d_in[0];
    float* out = (float*)d_out;
    dim3 g1((PRI + TPRI - 1) / TPRI, BATCH);
    k_decode<<<g1, 128>>>(x);
    k_class<<<BATCH*NC, BDIM>>>();
    k_det_raster<<<BATCH, BDIM>>>(out);
}